// round 4
// baseline (speedup 1.0000x reference)
#include <cuda_runtime.h>
#include <cuda_bf16.h>
#include <math.h>

#define SQ   1024      // sequence length
#define DM   1024      // model dim
#define NH   16        // heads
#define HD   64        // head dim
#define DFF  4096
#define NL   4
#define NV   32000

// ---------------- scratch (no allocations allowed) ----------------
__device__ float g_x  [SQ*DM];
__device__ float g_ex [SQ*DM];
__device__ float g_ain[SQ*DM];
__device__ float g_q  [SQ*DM];
__device__ float g_k  [SQ*DM];
__device__ float g_v  [SQ*DM];
__device__ float g_y  [SQ*DM];
__device__ float g_tmp[SQ*DM];
__device__ float g_h1 [SQ*DFF];
__device__ float g_h2 [SQ*DFF];

// ---------------- reductions ----------------
__device__ __forceinline__ float warp_sum(float v){
#pragma unroll
    for (int o = 16; o; o >>= 1) v += __shfl_xor_sync(0xffffffffu, v, o);
    return v;
}
__device__ __forceinline__ float warp_max(float v){
#pragma unroll
    for (int o = 16; o; o >>= 1) v = fmaxf(v, __shfl_xor_sync(0xffffffffu, v, o));
    return v;
}

// ---------------- embed gather + rms ----------------
__global__ void embed_rms_kernel(const int* __restrict__ ids,
                                 const float* __restrict__ embed,
                                 float* __restrict__ x, float* __restrict__ ex)
{
    __shared__ float red[8];
    int s = blockIdx.x;
    const float* row = embed + (long)ids[s] * DM;
    float ss = 0.f;
    for (int i = threadIdx.x; i < DM; i += 256) { float v = row[i]; ss += v*v; }
    ss = warp_sum(ss);
    if ((threadIdx.x & 31) == 0) red[threadIdx.x >> 5] = ss;
    __syncthreads();
    float tot = 0.f;
#pragma unroll
    for (int i = 0; i < 8; i++) tot += red[i];
    float rinv = rsqrtf(tot / (float)DM + 1e-5f);
    for (int i = threadIdx.x; i < DM; i += 256) {
        float v = row[i] * rinv;
        x[s*DM + i]  = v;
        ex[s*DM + i] = v;
    }
}

// ---------------- rms norm (row-wise) ----------------
__global__ void rms_kernel(const float* __restrict__ in, float* __restrict__ out)
{
    __shared__ float red[8];
    int s = blockIdx.x;
    const float* r = in + s*DM;
    float ss = 0.f;
    for (int i = threadIdx.x; i < DM; i += 256) { float v = r[i]; ss += v*v; }
    ss = warp_sum(ss);
    if ((threadIdx.x & 31) == 0) red[threadIdx.x >> 5] = ss;
    __syncthreads();
    float tot = 0.f;
#pragma unroll
    for (int i = 0; i < 8; i++) tot += red[i];
    float rinv = rsqrtf(tot / (float)DM + 1e-5f);
    for (int i = threadIdx.x; i < DM; i += 256) out[s*DM + i] = r[i]*rinv;
}

// ---------------- SGEMM: C[M,N] = alpha * A[M,K] * B[N,K]^T ----------------
// M = gridDim.y*128, N = gridDim.x*128, K multiple of 8. All row-major.
__global__ __launch_bounds__(256)
void gemm_nt(const float* __restrict__ A, const float* __restrict__ B,
             float* __restrict__ C, int K, int N,
             const float* __restrict__ alpha_ptr)
{
    __shared__ float As[8][128];
    __shared__ float Bs[8][128];
    int tid = threadIdx.x;
    int lr  = tid >> 1;            // 0..127 row within tile
    int lc  = (tid & 1) << 2;      // 0 or 4
    const float* Ab = A + (long)(blockIdx.y * 128) * K;
    const float* Bb = B + (long)(blockIdx.x * 128) * K;
    int tx = (tid & 15) << 3;      // 0..120 (col offset)
    int ty = (tid >> 4) << 3;      // 0..120 (row offset)

    float acc[8][8];
#pragma unroll
    for (int i = 0; i < 8; i++)
#pragma unroll
        for (int j = 0; j < 8; j++) acc[i][j] = 0.f;

    for (int k0 = 0; k0 < K; k0 += 8) {
        float4 a4 = *(const float4*)(Ab + (long)lr*K + k0 + lc);
        float4 b4 = *(const float4*)(Bb + (long)lr*K + k0 + lc);
        As[lc+0][lr] = a4.x; As[lc+1][lr] = a4.y; As[lc+2][lr] = a4.z; As[lc+3][lr] = a4.w;
        Bs[lc+0][lr] = b4.x; Bs[lc+1][lr] = b4.y; Bs[lc+2][lr] = b4.z; Bs[lc+3][lr] = b4.w;
        __syncthreads();
#pragma unroll
        for (int kk = 0; kk < 8; kk++) {
            float4 m0 = *(const float4*)&As[kk][ty];
            float4 m1 = *(const float4*)&As[kk][ty+4];
            float4 n0 = *(const float4*)&Bs[kk][tx];
            float4 n1 = *(const float4*)&Bs[kk][tx+4];
            float rm[8] = {m0.x,m0.y,m0.z,m0.w,m1.x,m1.y,m1.z,m1.w};
            float rn[8] = {n0.x,n0.y,n0.z,n0.w,n1.x,n1.y,n1.z,n1.w};
#pragma unroll
            for (int i = 0; i < 8; i++)
#pragma unroll
                for (int j = 0; j < 8; j++)
                    acc[i][j] = fmaf(rm[i], rn[j], acc[i][j]);
        }
        __syncthreads();
    }

    float alpha = alpha_ptr ? alpha_ptr[0] : 1.f;
    float* Cb = C + (long)(blockIdx.y*128 + ty) * N + blockIdx.x*128 + tx;
#pragma unroll
    for (int i = 0; i < 8; i++) {
        float4 c0 = make_float4(alpha*acc[i][0], alpha*acc[i][1], alpha*acc[i][2], alpha*acc[i][3]);
        float4 c1 = make_float4(alpha*acc[i][4], alpha*acc[i][5], alpha*acc[i][6], alpha*acc[i][7]);
        *(float4*)(Cb + (long)i*N)     = c0;
        *(float4*)(Cb + (long)i*N + 4) = c1;
    }
}

// ---------------- rope + per-head rms (+ optional head gain) ----------------
// buf layout [S, H, HD]; one warp per (s,h)
__global__ void rope_rms_kernel(float* __restrict__ buf, const float* __restrict__ gain)
{
    int h = blockIdx.x, s = blockIdx.y, lane = threadIdx.x;
    float* p = buf + ((long)s*NH + h)*HD;
    float x1 = p[lane], x2 = p[lane+32];
    // inv_freq = 10000^(-lane/32)
    float invf = expf(-((float)lane / 32.f) * 9.210340371976184f);
    float sn, c;
    sincosf((float)s * invf, &sn, &c);
    float o1 =  x1*c + x2*sn;
    float o2 = -x1*sn + x2*c;
    float ss = warp_sum(o1*o1 + o2*o2);
    float rinv = rsqrtf(ss / 64.f + 1e-5f);
    float g = gain ? gain[h] : 1.f;
    p[lane]    = o1*rinv*g;
    p[lane+32] = o2*rinv*g;
}

// ---------------- causal attention (flash-style, warp per query) ----------------
// q,k,v,y layout [S, H, HD]. Block = 8 warps = 8 queries of one head.
__global__ __launch_bounds__(256)
void attn_kernel(const float* __restrict__ q, const float* __restrict__ k,
                 const float* __restrict__ v, float* __restrict__ y)
{
    __shared__ float qs[8][65];
    __shared__ float ks[32][65];
    __shared__ float vs[32][65];
    int h   = blockIdx.y;
    int qb  = blockIdx.x;         // query block of 8
    int w   = threadIdx.x >> 5;
    int lane= threadIdx.x & 31;
    int qidx = qb*8 + w;

    for (int i = threadIdx.x; i < 8*HD; i += 256) {
        int r = i >> 6, c = i & 63;
        qs[r][c] = q[(((long)(qb*8 + r))*NH + h)*HD + c];
    }

    float m = -1e30f, lsum = 0.f, o0 = 0.f, o1 = 0.f;
    int qmax = qb*8 + 7;
    for (int kt = 0; kt <= qmax; kt += 32) {
        __syncthreads();
        for (int i = threadIdx.x; i < 32*HD; i += 256) {
            int r = i >> 6, c = i & 63;
            long off = (((long)(kt + r))*NH + h)*HD + c;
            ks[r][c] = k[off];
            vs[r][c] = v[off];
        }
        __syncthreads();
        int kk = kt + lane;
        float sc = 0.f;
#pragma unroll
        for (int d = 0; d < HD; d++) sc = fmaf(qs[w][d], ks[lane][d], sc);
        sc *= 0.125f;
        if (kk > qidx) sc = -1e30f;
        float tmax = warp_max(sc);
        float mnew = fmaxf(m, tmax);
        float p = expf(sc - mnew);          // masked -> exp(very negative)=0
        float corr = expf(m - mnew);
        m = mnew;
        float psum = warp_sum(p);
        lsum = lsum*corr + psum;
        o0 *= corr; o1 *= corr;
#pragma unroll
        for (int j = 0; j < 32; j++) {
            float pj = __shfl_sync(0xffffffffu, p, j);
            o0 = fmaf(pj, vs[j][lane],    o0);
            o1 = fmaf(pj, vs[j][lane+32], o1);
        }
    }
    float inv = 1.f / lsum;
    y[((long)qidx*NH + h)*HD + lane]      = o0*inv;
    y[((long)qidx*NH + h)*HD + lane + 32] = o1*inv;
}

// ---------------- elementwise ----------------
__global__ void axpy_gain_kernel(float* __restrict__ x, const float* __restrict__ t,
                                 const float* __restrict__ gain, int n)
{
    int i = blockIdx.x*256 + threadIdx.x;
    if (i < n) x[i] = fmaf(t[i], gain[0], x[i]);
}
__global__ void silu_mul_kernel(float* __restrict__ a, const float* __restrict__ b, int n)
{
    int i = blockIdx.x*256 + threadIdx.x;
    if (i < n) {
        float g = a[i];
        a[i] = (g / (1.f + expf(-g))) * b[i];
    }
}
__global__ void residual2_kernel(float* __restrict__ x, const float* __restrict__ t,
                                 const float* __restrict__ ex,
                                 const float* __restrict__ mg, const float* __restrict__ sk, int n)
{
    int i = blockIdx.x*256 + threadIdx.x;
    if (i < n) x[i] = x[i] + t[i]*mg[0] + ex[i]*sk[0];
}

// ---------------- launch ----------------
extern "C" void kernel_launch(void* const* d_in, const int* in_sizes, int n_in,
                              void* d_out, int out_size)
{
    const int*   ids        = (const int*)  d_in[0];
    const float* embed      = (const float*)d_in[1];
    const float* Wq         = (const float*)d_in[2];
    const float* Wk         = (const float*)d_in[3];
    const float* Wv         = (const float*)d_in[4];
    const float* Wo         = (const float*)d_in[5];
    const float* head_gain  = (const float*)d_in[6];
    const float* attn_gain  = (const float*)d_in[7];
    const float* Wg         = (const float*)d_in[8];
    const float* Wl         = (const float*)d_in[9];
    const float* Wr         = (const float*)d_in[10];
    const float* mlp_gain   = (const float*)d_in[11];
    const float* embed_skip = (const float*)d_in[12];
    const float* lm_head    = (const float*)d_in[13];
    const float* lm_gain    = (const float*)d_in[14];

    float *x,*ex,*ain,*q,*k,*v,*y,*tmp,*h1,*h2;
    cudaGetSymbolAddress((void**)&x,   g_x);
    cudaGetSymbolAddress((void**)&ex,  g_ex);
    cudaGetSymbolAddress((void**)&ain, g_ain);
    cudaGetSymbolAddress((void**)&q,   g_q);
    cudaGetSymbolAddress((void**)&k,   g_k);
    cudaGetSymbolAddress((void**)&v,   g_v);
    cudaGetSymbolAddress((void**)&y,   g_y);
    cudaGetSymbolAddress((void**)&tmp, g_tmp);
    cudaGetSymbolAddress((void**)&h1,  g_h1);
    cudaGetSymbolAddress((void**)&h2,  g_h2);

    dim3 g_dd(DM/128, SQ/128);     // 1024x1024 GEMMs
    dim3 g_ff(DFF/128, SQ/128);    // 1024x4096 GEMMs
    dim3 g_lm(NV/128, SQ/128);     // 1024x32000 GEMM
    dim3 g_rope(NH, SQ);
    dim3 g_attn(SQ/8, NH);
    int nd  = SQ*DM,  bd  = nd/256;
    int nff = SQ*DFF, bff = nff/256;

    embed_rms_kernel<<<SQ, 256>>>(ids, embed, x, ex);

    for (int l = 0; l < NL; l++) {
        rms_kernel<<<SQ, 256>>>(x, ain);
        gemm_nt<<<g_dd, 256>>>(ain, Wq + (long)l*DM*DM, q, DM, DM, nullptr);
        gemm_nt<<<g_dd, 256>>>(ain, Wk + (long)l*DM*DM, k, DM, DM, nullptr);
        gemm_nt<<<g_dd, 256>>>(ain, Wv + (long)l*DM*DM, v, DM, DM, nullptr);
        rope_rms_kernel<<<g_rope, 32>>>(q, head_gain + l*NH);
        rope_rms_kernel<<<g_rope, 32>>>(k, nullptr);
        attn_kernel<<<g_attn, 256>>>(q, k, v, y);
        gemm_nt<<<g_dd, 256>>>(y, Wo + (long)l*DM*DM, tmp, DM, DM, nullptr);
        axpy_gain_kernel<<<bd, 256>>>(x, tmp, attn_gain + l, nd);
        rms_kernel<<<SQ, 256>>>(x, ain);
        gemm_nt<<<g_ff, 256>>>(ain, Wg + (long)l*DFF*DM, h1, DM, DFF, nullptr);
        gemm_nt<<<g_ff, 256>>>(ain, Wl + (long)l*DFF*DM, h2, DM, DFF, nullptr);
        silu_mul_kernel<<<bff, 256>>>(h1, h2, nff);
        gemm_nt<<<g_dd, 256>>>(h1, Wr + (long)l*DM*DFF, tmp, DFF, DM, nullptr);
        residual2_kernel<<<bd, 256>>>(x, tmp, ex, mlp_gain + l, embed_skip + l, nd);
    }

    rms_kernel<<<SQ, 256>>>(x, ain);
    gemm_nt<<<g_lm, 256>>>(ain, lm_head, (float*)d_out, DM, NV, lm_gain);
}

// round 8
// speedup vs baseline: 2.7813x; 2.7813x over previous
#include <cuda_runtime.h>
#include <cuda_bf16.h>
#include <math.h>
#include <stdint.h>

#define SQ   1024
#define DM   1024
#define NH   16
#define HD   64
#define DFF  4096
#define NL   4
#define NV   32000

// ---------------- scratch (no allocations allowed) ----------------
__device__ float g_x  [SQ*DM];
__device__ float g_ex [SQ*DM];
__device__ float g_ain[SQ*DM];
__device__ float g_q  [SQ*DM];
__device__ float g_k  [SQ*DM];
__device__ float g_v  [SQ*DM];
__device__ float g_y  [SQ*DM];
__device__ float g_tmp[SQ*DM];
__device__ float g_h1 [SQ*DFF];
__device__ float g_h2 [SQ*DFF];

// ---------------- helpers ----------------
__device__ __forceinline__ uint32_t f2tf32(float f){
    uint32_t u; asm("cvt.rna.tf32.f32 %0, %1;" : "=r"(u) : "f"(f)); return u;
}
__device__ __forceinline__ void mma16n8k8(float* c, const uint32_t* a, const uint32_t* b){
    asm volatile("mma.sync.aligned.m16n8k8.row.col.f32.tf32.tf32.f32 "
        "{%0,%1,%2,%3}, {%4,%5,%6,%7}, {%8,%9}, {%0,%1,%2,%3};"
        : "+f"(c[0]), "+f"(c[1]), "+f"(c[2]), "+f"(c[3])
        : "r"(a[0]), "r"(a[1]), "r"(a[2]), "r"(a[3]), "r"(b[0]), "r"(b[1]));
}

// ---------------- tf32 tensor-core GEMM: C[M,N] = alpha * A[M,K] * B[N,K]^T ----------------
// grid = (N/BN, M/128), 256 threads. K multiple of 32, all row-major fp32.
template<int BN>
__global__ __launch_bounds__(256)
void gemm_mma(const float* __restrict__ A, const float* __restrict__ B,
              float* __restrict__ C, int K, int N, const float* __restrict__ alpha_ptr)
{
    constexpr int BM  = 128;
    constexpr int BK  = 32;
    constexpr int LDSF= BK + 4;          // 36 floats per smem row (conflict-free)
    constexpr int WN  = BN / 2;          // warp n-tile (warps laid out 4m x 2n)
    constexpr int NT  = WN / 8;          // n mma-tiles per warp
    constexpr int NA4 = 4;               // A float4 slots per thread (128*8/256)
    constexpr int NB4 = BN * 8 / 256;    // B float4 slots per thread

    extern __shared__ float sm[];
    float* As = sm;                      // [2][BM][LDSF]
    float* Bs = sm + 2 * BM * LDSF;      // [2][BN][LDSF]

    int tid  = threadIdx.x;
    int lane = tid & 31;
    int w    = tid >> 5;
    int wm   = (w & 3) * 32;             // warp m base within tile
    int wn   = (w >> 2) * WN;            // warp n base within tile
    int lg   = lane >> 2;                // group id 0..7
    int lt   = lane & 3;                 // thread-in-group 0..3

    const float* Ab = A + (size_t)(blockIdx.y * BM) * K;
    const float* Bb = B + (size_t)(blockIdx.x * BN) * K;

    // prefetch chunk 0 into registers
    float4 ra[NA4], rb[NB4];
#pragma unroll
    for (int j = 0; j < NA4; j++){
        int slot = tid + 256*j, row = slot >> 3, c4 = slot & 7;
        ra[j] = *(const float4*)(Ab + (size_t)row*K + c4*4);
    }
#pragma unroll
    for (int j = 0; j < NB4; j++){
        int slot = tid + 256*j, row = slot >> 3, c4 = slot & 7;
        rb[j] = *(const float4*)(Bb + (size_t)row*K + c4*4);
    }

    float acc[2][NT][4];
#pragma unroll
    for (int m = 0; m < 2; m++)
#pragma unroll
        for (int n = 0; n < NT; n++)
#pragma unroll
            for (int i = 0; i < 4; i++) acc[m][n][i] = 0.f;

    int nchunk = K / BK;
    for (int c = 0; c < nchunk; c++){
        int st = c & 1;
        float* as = As + st * BM * LDSF;
        float* bs = Bs + st * BN * LDSF;

        // convert + store current chunk into smem
#pragma unroll
        for (int j = 0; j < NA4; j++){
            int slot = tid + 256*j, row = slot >> 3, c4 = slot & 7;
            uint4 v = make_uint4(f2tf32(ra[j].x), f2tf32(ra[j].y), f2tf32(ra[j].z), f2tf32(ra[j].w));
            *(uint4*)(as + row*LDSF + c4*4) = v;
        }
#pragma unroll
        for (int j = 0; j < NB4; j++){
            int slot = tid + 256*j, row = slot >> 3, c4 = slot & 7;
            uint4 v = make_uint4(f2tf32(rb[j].x), f2tf32(rb[j].y), f2tf32(rb[j].z), f2tf32(rb[j].w));
            *(uint4*)(bs + row*LDSF + c4*4) = v;
        }

        // prefetch next chunk
        if (c + 1 < nchunk){
            const float* An = Ab + (size_t)(c+1)*BK;
            const float* Bn = Bb + (size_t)(c+1)*BK;
#pragma unroll
            for (int j = 0; j < NA4; j++){
                int slot = tid + 256*j, row = slot >> 3, c4 = slot & 7;
                ra[j] = *(const float4*)(An + (size_t)row*K + c4*4);
            }
#pragma unroll
            for (int j = 0; j < NB4; j++){
                int slot = tid + 256*j, row = slot >> 3, c4 = slot & 7;
                rb[j] = *(const float4*)(Bn + (size_t)row*K + c4*4);
            }
        }
        __syncthreads();

        const uint32_t* asu = (const uint32_t*)as;
        const uint32_t* bsu = (const uint32_t*)bs;
#pragma unroll
        for (int ks = 0; ks < 4; ks++){
            int kb = ks * 8;
            uint32_t af[2][4];
#pragma unroll
            for (int m = 0; m < 2; m++){
                const uint32_t* ap = asu + (wm + m*16 + lg)*LDSF + kb + lt;
                af[m][0] = ap[0];
                af[m][1] = ap[8*LDSF];
                af[m][2] = ap[4];
                af[m][3] = ap[8*LDSF + 4];
            }
#pragma unroll
            for (int n = 0; n < NT; n++){
                const uint32_t* bp = bsu + (wn + n*8 + lg)*LDSF + kb + lt;
                uint32_t bf[2] = { bp[0], bp[4] };
                mma16n8k8(acc[0][n], af[0], bf);
                mma16n8k8(acc[1][n], af[1], bf);
            }
        }
        __syncthreads();
    }

    float alpha = alpha_ptr ? alpha_ptr[0] : 1.f;
    int row0 = blockIdx.y*BM + wm + lg;
    int col0 = blockIdx.x*BN + wn + 2*lt;
#pragma unroll
    for (int m = 0; m < 2; m++){
#pragma unroll
        for (int n = 0; n < NT; n++){
            float2 v0 = make_float2(alpha*acc[m][n][0], alpha*acc[m][n][1]);
            float2 v1 = make_float2(alpha*acc[m][n][2], alpha*acc[m][n][3]);
            *(float2*)(C + (size_t)(row0 + m*16    )*N + col0 + n*8) = v0;
            *(float2*)(C + (size_t)(row0 + m*16 + 8)*N + col0 + n*8) = v1;
        }
    }
}

#define SMEM64  (2*(128+64) *36*4)
#define SMEM128 (2*(128+128)*36*4)

// ---------------- reductions ----------------
__device__ __forceinline__ float warp_sum(float v){
#pragma unroll
    for (int o = 16; o; o >>= 1) v += __shfl_xor_sync(0xffffffffu, v, o);
    return v;
}
__device__ __forceinline__ float warp_max(float v){
#pragma unroll
    for (int o = 16; o; o >>= 1) v = fmaxf(v, __shfl_xor_sync(0xffffffffu, v, o));
    return v;
}

// ---------------- embed gather + rms ----------------
__global__ void embed_rms_kernel(const int* __restrict__ ids,
                                 const float* __restrict__ embed,
                                 float* __restrict__ x, float* __restrict__ ex)
{
    __shared__ float red[8];
    int s = blockIdx.x;
    const float* row = embed + (long)ids[s] * DM;
    float ss = 0.f;
    for (int i = threadIdx.x; i < DM; i += 256) { float v = row[i]; ss += v*v; }
    ss = warp_sum(ss);
    if ((threadIdx.x & 31) == 0) red[threadIdx.x >> 5] = ss;
    __syncthreads();
    float tot = 0.f;
#pragma unroll
    for (int i = 0; i < 8; i++) tot += red[i];
    float rinv = rsqrtf(tot / (float)DM + 1e-5f);
    for (int i = threadIdx.x; i < DM; i += 256) {
        float v = row[i] * rinv;
        x[s*DM + i]  = v;
        ex[s*DM + i] = v;
    }
}

// ---------------- rms norm (row-wise) ----------------
__global__ void rms_kernel(const float* __restrict__ in, float* __restrict__ out)
{
    __shared__ float red[8];
    int s = blockIdx.x;
    const float* r = in + s*DM;
    float ss = 0.f;
    for (int i = threadIdx.x; i < DM; i += 256) { float v = r[i]; ss += v*v; }
    ss = warp_sum(ss);
    if ((threadIdx.x & 31) == 0) red[threadIdx.x >> 5] = ss;
    __syncthreads();
    float tot = 0.f;
#pragma unroll
    for (int i = 0; i < 8; i++) tot += red[i];
    float rinv = rsqrtf(tot / (float)DM + 1e-5f);
    for (int i = threadIdx.x; i < DM; i += 256) out[s*DM + i] = r[i]*rinv;
}

// ---------------- rope + per-head rms (+ optional head gain) ----------------
__global__ void rope_rms_kernel(float* __restrict__ buf, const float* __restrict__ gain)
{
    int h = blockIdx.x, s = blockIdx.y, lane = threadIdx.x;
    float* p = buf + ((long)s*NH + h)*HD;
    float x1 = p[lane], x2 = p[lane+32];
    float invf = expf(-((float)lane / 32.f) * 9.210340371976184f);
    float sn, c;
    sincosf((float)s * invf, &sn, &c);
    float o1 =  x1*c + x2*sn;
    float o2 = -x1*sn + x2*c;
    float ss = warp_sum(o1*o1 + o2*o2);
    float rinv = rsqrtf(ss / 64.f + 1e-5f);
    float g = gain ? gain[h] : 1.f;
    p[lane]    = o1*rinv*g;
    p[lane+32] = o2*rinv*g;
}

// ---------------- causal attention (flash-style, warp per query) ----------------
__global__ __launch_bounds__(256)
void attn_kernel(const float* __restrict__ q, const float* __restrict__ k,
                 const float* __restrict__ v, float* __restrict__ y)
{
    __shared__ float qs[8][65];
    __shared__ float ks[32][65];
    __shared__ float vs[32][65];
    int h   = blockIdx.y;
    int qb  = blockIdx.x;
    int w   = threadIdx.x >> 5;
    int lane= threadIdx.x & 31;
    int qidx = qb*8 + w;

    for (int i = threadIdx.x; i < 8*HD; i += 256) {
        int r = i >> 6, c = i & 63;
        qs[r][c] = q[(((long)(qb*8 + r))*NH + h)*HD + c];
    }

    float m = -1e30f, lsum = 0.f, o0 = 0.f, o1 = 0.f;
    int qmax = qb*8 + 7;
    for (int kt = 0; kt <= qmax; kt += 32) {
        __syncthreads();
        for (int i = threadIdx.x; i < 32*HD; i += 256) {
            int r = i >> 6, c = i & 63;
            long off = (((long)(kt + r))*NH + h)*HD + c;
            ks[r][c] = k[off];
            vs[r][c] = v[off];
        }
        __syncthreads();
        int kk = kt + lane;
        float sc = 0.f;
#pragma unroll
        for (int d = 0; d < HD; d++) sc = fmaf(qs[w][d], ks[lane][d], sc);
        sc *= 0.125f;
        if (kk > qidx) sc = -1e30f;
        float tmax = warp_max(sc);
        float mnew = fmaxf(m, tmax);
        float p = expf(sc - mnew);
        float corr = expf(m - mnew);
        m = mnew;
        float psum = warp_sum(p);
        lsum = lsum*corr + psum;
        o0 *= corr; o1 *= corr;
#pragma unroll
        for (int j = 0; j < 32; j++) {
            float pj = __shfl_sync(0xffffffffu, p, j);
            o0 = fmaf(pj, vs[j][lane],    o0);
            o1 = fmaf(pj, vs[j][lane+32], o1);
        }
    }
    float inv = 1.f / lsum;
    y[((long)qidx*NH + h)*HD + lane]      = o0*inv;
    y[((long)qidx*NH + h)*HD + lane + 32] = o1*inv;
}

// ---------------- elementwise ----------------
__global__ void axpy_gain_kernel(float* __restrict__ x, const float* __restrict__ t,
                                 const float* __restrict__ gain, int n)
{
    int i = blockIdx.x*256 + threadIdx.x;
    if (i < n) x[i] = fmaf(t[i], gain[0], x[i]);
}
__global__ void silu_mul_kernel(float* __restrict__ a, const float* __restrict__ b, int n)
{
    int i = blockIdx.x*256 + threadIdx.x;
    if (i < n) {
        float g = a[i];
        a[i] = (g / (1.f + expf(-g))) * b[i];
    }
}
__global__ void residual2_kernel(float* __restrict__ x, const float* __restrict__ t,
                                 const float* __restrict__ ex,
                                 const float* __restrict__ mg, const float* __restrict__ sk, int n)
{
    int i = blockIdx.x*256 + threadIdx.x;
    if (i < n) x[i] = x[i] + t[i]*mg[0] + ex[i]*sk[0];
}

// ---------------- launch ----------------
extern "C" void kernel_launch(void* const* d_in, const int* in_sizes, int n_in,
                              void* d_out, int out_size)
{
    const int*   ids        = (const int*)  d_in[0];
    const float* embed      = (const float*)d_in[1];
    const float* Wq         = (const float*)d_in[2];
    const float* Wk         = (const float*)d_in[3];
    const float* Wv         = (const float*)d_in[4];
    const float* Wo         = (const float*)d_in[5];
    const float* head_gain  = (const float*)d_in[6];
    const float* attn_gain  = (const float*)d_in[7];
    const float* Wg         = (const float*)d_in[8];
    const float* Wl         = (const float*)d_in[9];
    const float* Wr         = (const float*)d_in[10];
    const float* mlp_gain   = (const float*)d_in[11];
    const float* embed_skip = (const float*)d_in[12];
    const float* lm_head    = (const float*)d_in[13];
    const float* lm_gain    = (const float*)d_in[14];

    float *x,*ex,*ain,*q,*k,*v,*y,*tmp,*h1,*h2;
    cudaGetSymbolAddress((void**)&x,   g_x);
    cudaGetSymbolAddress((void**)&ex,  g_ex);
    cudaGetSymbolAddress((void**)&ain, g_ain);
    cudaGetSymbolAddress((void**)&q,   g_q);
    cudaGetSymbolAddress((void**)&k,   g_k);
    cudaGetSymbolAddress((void**)&v,   g_v);
    cudaGetSymbolAddress((void**)&y,   g_y);
    cudaGetSymbolAddress((void**)&tmp, g_tmp);
    cudaGetSymbolAddress((void**)&h1,  g_h1);
    cudaGetSymbolAddress((void**)&h2,  g_h2);

    cudaFuncSetAttribute(gemm_mma<64>,  cudaFuncAttributeMaxDynamicSharedMemorySize, SMEM64);
    cudaFuncSetAttribute(gemm_mma<128>, cudaFuncAttributeMaxDynamicSharedMemorySize, SMEM128);

    dim3 g_dd(DM/64,  SQ/128);     // N=1024 GEMMs: 16x8 = 128 CTAs
    dim3 g_ff(DFF/128, SQ/128);    // N=4096 GEMMs: 32x8 = 256 CTAs
    dim3 g_lm(NV/128,  SQ/128);    // N=32000 GEMM: 250x8 = 2000 CTAs
    dim3 g_rope(NH, SQ);
    dim3 g_attn(SQ/8, NH);
    int nd  = SQ*DM,  bd  = nd/256;
    int nff = SQ*DFF, bff = nff/256;

    embed_rms_kernel<<<SQ, 256>>>(ids, embed, x, ex);

    for (int l = 0; l < NL; l++) {
        rms_kernel<<<SQ, 256>>>(x, ain);
        gemm_mma<64><<<g_dd, 256, SMEM64>>>(ain, Wq + (long)l*DM*DM, q, DM, DM, nullptr);
        gemm_mma<64><<<g_dd, 256, SMEM64>>>(ain, Wk + (long)l*DM*DM, k, DM, DM, nullptr);
        gemm_mma<64><<<g_dd, 256, SMEM64>>>(ain, Wv + (long)l*DM*DM, v, DM, DM, nullptr);
        rope_rms_kernel<<<g_rope, 32>>>(q, head_gain + l*NH);
        rope_rms_kernel<<<g_rope, 32>>>(k, nullptr);
        attn_kernel<<<g_attn, 256>>>(q, k, v, y);
        gemm_mma<64><<<g_dd, 256, SMEM64>>>(y, Wo + (long)l*DM*DM, tmp, DM, DM, nullptr);
        axpy_gain_kernel<<<bd, 256>>>(x, tmp, attn_gain + l, nd);
        rms_kernel<<<SQ, 256>>>(x, ain);
        gemm_mma<128><<<g_ff, 256, SMEM128>>>(ain, Wg + (long)l*DFF*DM, h1, DM, DFF, nullptr);
        gemm_mma<128><<<g_ff, 256, SMEM128>>>(ain, Wl + (long)l*DFF*DM, h2, DM, DFF, nullptr);
        silu_mul_kernel<<<bff, 256>>>(h1, h2, nff);
        gemm_mma<64><<<g_dd, 256, SMEM64>>>(h1, Wr + (long)l*DM*DFF, tmp, DFF, DM, nullptr);
        residual2_kernel<<<bd, 256>>>(x, tmp, ex, mlp_gain + l, embed_skip + l, nd);
    }

    rms_kernel<<<SQ, 256>>>(x, ain);
    gemm_mma<128><<<g_lm, 256, SMEM128>>>(ain, lm_head, (float*)d_out, DM, NV, lm_gain);
}

// round 15
// speedup vs baseline: 3.1943x; 1.1485x over previous
#include <cuda_runtime.h>
#include <cuda_bf16.h>
#include <math.h>
#include <stdint.h>

#define SQ   1024
#define DM   1024
#define NH   16
#define HD   64
#define DFF  4096
#define NL   4
#define NV   32000

// ---------------- scratch (no allocations allowed) ----------------
__device__ float g_x  [SQ*DM];
__device__ float g_ex [SQ*DM];
__device__ float g_ain[SQ*DM];
__device__ float g_q  [SQ*DM];
__device__ float g_k  [SQ*DM];
__device__ float g_v  [SQ*DM];
__device__ float g_y  [SQ*DM];
__device__ float g_tmp[2*SQ*DM];      // split-K partials
__device__ float g_h1 [SQ*DFF];
__device__ float g_h2 [SQ*DFF];

// ---------------- helpers ----------------
__device__ __forceinline__ uint32_t f2tf32(float f){
    uint32_t u; asm("cvt.rna.tf32.f32 %0, %1;" : "=r"(u) : "f"(f)); return u;
}
__device__ __forceinline__ void mma16n8k8(float* c, const uint32_t* a, const uint32_t* b){
    asm volatile("mma.sync.aligned.m16n8k8.row.col.f32.tf32.tf32.f32 "
        "{%0,%1,%2,%3}, {%4,%5,%6,%7}, {%8,%9}, {%0,%1,%2,%3};"
        : "+f"(c[0]), "+f"(c[1]), "+f"(c[2]), "+f"(c[3])
        : "r"(a[0]), "r"(a[1]), "r"(a[2]), "r"(a[3]), "r"(b[0]), "r"(b[1]));
}

// ---------------- tf32 tensor-core GEMM: C[M,N] = alpha * A[M,K] * B[N,K]^T ----------------
// grid = (N/BN, M/128, Z). Z-axis dual use:
//   k0mul == 0 : multi-operand mode. z selects (B0,C0)/(B1,C1)/(B2,C2), full K.
//   k0mul  > 0 : split-K mode. B = B0 always; z computes K range [z*k0mul, (z+1)*k0mul),
//                C = (z==0 ? C0 : C1) holds partial products.
// 256 threads, K multiple of 32, all row-major fp32.
template<int BN>
__global__ __launch_bounds__(256, 2)
void gemm_mma(const float* __restrict__ A,
              const float* __restrict__ B0, const float* __restrict__ B1, const float* __restrict__ B2,
              float* __restrict__ C0, float* __restrict__ C1, float* __restrict__ C2,
              int K, int N, const float* __restrict__ alpha_ptr, int k0mul)
{
    constexpr int BM  = 128;
    constexpr int BK  = 32;
    constexpr int LDSF= BK + 4;          // 36 floats per smem row (conflict-free)
    constexpr int WN  = BN / 2;          // warp n-tile (warps laid out 4m x 2n)
    constexpr int NT  = WN / 8;          // n mma-tiles per warp
    constexpr int NA4 = 4;               // A float4 slots per thread (128*8/256)
    constexpr int NB4 = BN * 8 / 256;    // B float4 slots per thread

    extern __shared__ float sm[];
    float* As = sm;                      // [2][BM][LDSF]
    float* Bs = sm + 2 * BM * LDSF;      // [2][BN][LDSF]

    int z = blockIdx.z;
    const float* B;
    float*       C;
    int k0, klen;
    if (k0mul > 0){                      // split-K: same B, partial outputs
        B    = B0;
        C    = (z == 0) ? C0 : C1;
        k0   = k0mul * z;
        klen = k0mul;
    } else {                             // multi-operand: z selects B/C pair
        B    = (z == 0) ? B0 : ((z == 1) ? B1 : B2);
        C    = (z == 0) ? C0 : ((z == 1) ? C1 : C2);
        k0   = 0;
        klen = K;
    }

    int tid  = threadIdx.x;
    int lane = tid & 31;
    int w    = tid >> 5;
    int wm   = (w & 3) * 32;             // warp m base within tile
    int wn   = (w >> 2) * WN;            // warp n base within tile
    int lg   = lane >> 2;                // group id 0..7
    int lt   = lane & 3;                 // thread-in-group 0..3

    const float* Ab = A + (size_t)(blockIdx.y * BM) * K + k0;
    const float* Bb = B + (size_t)(blockIdx.x * BN) * K + k0;

    // prefetch chunk 0 into registers
    float4 ra[NA4], rb[NB4];
#pragma unroll
    for (int j = 0; j < NA4; j++){
        int slot = tid + 256*j, row = slot >> 3, c4 = slot & 7;
        ra[j] = *(const float4*)(Ab + (size_t)row*K + c4*4);
    }
#pragma unroll
    for (int j = 0; j < NB4; j++){
        int slot = tid + 256*j, row = slot >> 3, c4 = slot & 7;
        rb[j] = *(const float4*)(Bb + (size_t)row*K + c4*4);
    }

    float acc[2][NT][4];
#pragma unroll
    for (int m = 0; m < 2; m++)
#pragma unroll
        for (int n = 0; n < NT; n++)
#pragma unroll
            for (int i = 0; i < 4; i++) acc[m][n][i] = 0.f;

    int nchunk = klen / BK;
    for (int c = 0; c < nchunk; c++){
        int st = c & 1;
        float* as = As + st * BM * LDSF;
        float* bs = Bs + st * BN * LDSF;

        // convert + store current chunk into smem
#pragma unroll
        for (int j = 0; j < NA4; j++){
            int slot = tid + 256*j, row = slot >> 3, c4 = slot & 7;
            uint4 v = make_uint4(f2tf32(ra[j].x), f2tf32(ra[j].y), f2tf32(ra[j].z), f2tf32(ra[j].w));
            *(uint4*)(as + row*LDSF + c4*4) = v;
        }
#pragma unroll
        for (int j = 0; j < NB4; j++){
            int slot = tid + 256*j, row = slot >> 3, c4 = slot & 7;
            uint4 v = make_uint4(f2tf32(rb[j].x), f2tf32(rb[j].y), f2tf32(rb[j].z), f2tf32(rb[j].w));
            *(uint4*)(bs + row*LDSF + c4*4) = v;
        }

        // prefetch next chunk
        if (c + 1 < nchunk){
            const float* An = Ab + (size_t)(c+1)*BK;
            const float* Bn = Bb + (size_t)(c+1)*BK;
#pragma unroll
            for (int j = 0; j < NA4; j++){
                int slot = tid + 256*j, row = slot >> 3, c4 = slot & 7;
                ra[j] = *(const float4*)(An + (size_t)row*K + c4*4);
            }
#pragma unroll
            for (int j = 0; j < NB4; j++){
                int slot = tid + 256*j, row = slot >> 3, c4 = slot & 7;
                rb[j] = *(const float4*)(Bn + (size_t)row*K + c4*4);
            }
        }
        __syncthreads();

        const uint32_t* asu = (const uint32_t*)as;
        const uint32_t* bsu = (const uint32_t*)bs;
#pragma unroll
        for (int ks = 0; ks < 4; ks++){
            int kb = ks * 8;
            uint32_t af[2][4];
#pragma unroll
            for (int m = 0; m < 2; m++){
                const uint32_t* ap = asu + (wm + m*16 + lg)*LDSF + kb + lt;
                af[m][0] = ap[0];
                af[m][1] = ap[8*LDSF];
                af[m][2] = ap[4];
                af[m][3] = ap[8*LDSF + 4];
            }
#pragma unroll
            for (int n = 0; n < NT; n++){
                const uint32_t* bp = bsu + (wn + n*8 + lg)*LDSF + kb + lt;
                uint32_t bf[2] = { bp[0], bp[4] };
                mma16n8k8(acc[0][n], af[0], bf);
                mma16n8k8(acc[1][n], af[1], bf);
            }
        }
        __syncthreads();
    }

    float alpha = alpha_ptr ? alpha_ptr[0] : 1.f;
    int row0 = blockIdx.y*BM + wm + lg;
    int col0 = blockIdx.x*BN + wn + 2*lt;
#pragma unroll
    for (int m = 0; m < 2; m++){
#pragma unroll
        for (int n = 0; n < NT; n++){
            float2 v0 = make_float2(alpha*acc[m][n][0], alpha*acc[m][n][1]);
            float2 v1 = make_float2(alpha*acc[m][n][2], alpha*acc[m][n][3]);
            *(float2*)(C + (size_t)(row0 + m*16    )*N + col0 + n*8) = v0;
            *(float2*)(C + (size_t)(row0 + m*16 + 8)*N + col0 + n*8) = v1;
        }
    }
}

#define SMEM64  (2*(128+64) *36*4)
#define SMEM128 (2*(128+128)*36*4)

// ---------------- reductions ----------------
__device__ __forceinline__ float warp_sum(float v){
#pragma unroll
    for (int o = 16; o; o >>= 1) v += __shfl_xor_sync(0xffffffffu, v, o);
    return v;
}
__device__ __forceinline__ float warp_max(float v){
#pragma unroll
    for (int o = 16; o; o >>= 1) v = fmaxf(v, __shfl_xor_sync(0xffffffffu, v, o));
    return v;
}

// ---------------- embed gather + rms ----------------
__global__ void embed_rms_kernel(const int* __restrict__ ids,
                                 const float* __restrict__ embed,
                                 float* __restrict__ x, float* __restrict__ ex)
{
    __shared__ float red[8];
    int s = blockIdx.x;
    const float* row = embed + (long)ids[s] * DM;
    float ss = 0.f;
    for (int i = threadIdx.x; i < DM; i += 256) { float v = row[i]; ss += v*v; }
    ss = warp_sum(ss);
    if ((threadIdx.x & 31) == 0) red[threadIdx.x >> 5] = ss;
    __syncthreads();
    float tot = 0.f;
#pragma unroll
    for (int i = 0; i < 8; i++) tot += red[i];
    float rinv = rsqrtf(tot / (float)DM + 1e-5f);
    for (int i = threadIdx.x; i < DM; i += 256) {
        float v = row[i] * rinv;
        x[s*DM + i]  = v;
        ex[s*DM + i] = v;
    }
}

// ---------------- rms norm (row-wise) ----------------
__global__ void rms_kernel(const float* __restrict__ in, float* __restrict__ out)
{
    __shared__ float red[8];
    int s = blockIdx.x;
    const float* r = in + s*DM;
    float ss = 0.f;
    for (int i = threadIdx.x; i < DM; i += 256) { float v = r[i]; ss += v*v; }
    ss = warp_sum(ss);
    if ((threadIdx.x & 31) == 0) red[threadIdx.x >> 5] = ss;
    __syncthreads();
    float tot = 0.f;
#pragma unroll
    for (int i = 0; i < 8; i++) tot += red[i];
    float rinv = rsqrtf(tot / (float)DM + 1e-5f);
    for (int i = threadIdx.x; i < DM; i += 256) out[s*DM + i] = r[i]*rinv;
}

// ---------------- rope + per-head rms (+ optional head gain) ----------------
__global__ void rope_rms_kernel(float* __restrict__ buf, const float* __restrict__ gain)
{
    int h = blockIdx.x, s = blockIdx.y, lane = threadIdx.x;
    float* p = buf + ((long)s*NH + h)*HD;
    float x1 = p[lane], x2 = p[lane+32];
    float invf = expf(-((float)lane / 32.f) * 9.210340371976184f);
    float sn, c;
    sincosf((float)s * invf, &sn, &c);
    float o1 =  x1*c + x2*sn;
    float o2 = -x1*sn + x2*c;
    float ss = warp_sum(o1*o1 + o2*o2);
    float rinv = rsqrtf(ss / 64.f + 1e-5f);
    float g = gain ? gain[h] : 1.f;
    p[lane]    = o1*rinv*g;
    p[lane+32] = o2*rinv*g;
}

// ---------------- causal attention (flash-style, warp per query) ----------------
__global__ __launch_bounds__(256)
void attn_kernel(const float* __restrict__ q, const float* __restrict__ k,
                 const float* __restrict__ v, float* __restrict__ y)
{
    __shared__ float qs[8][65];
    __shared__ float ks[32][65];
    __shared__ float vs[32][65];
    int h   = blockIdx.y;
    int qb  = blockIdx.x;
    int w   = threadIdx.x >> 5;
    int lane= threadIdx.x & 31;
    int qidx = qb*8 + w;

    for (int i = threadIdx.x; i < 8*HD; i += 256) {
        int r = i >> 6, c = i & 63;
        qs[r][c] = q[(((long)(qb*8 + r))*NH + h)*HD + c];
    }

    float m = -1e30f, lsum = 0.f, o0 = 0.f, o1 = 0.f;
    int qmax = qb*8 + 7;
    for (int kt = 0; kt <= qmax; kt += 32) {
        __syncthreads();
        for (int i = threadIdx.x; i < 32*HD; i += 256) {
            int r = i >> 6, c = i & 63;
            long off = (((long)(kt + r))*NH + h)*HD + c;
            ks[r][c] = k[off];
            vs[r][c] = v[off];
        }
        __syncthreads();
        int kk = kt + lane;
        float sc = 0.f;
#pragma unroll
        for (int d = 0; d < HD; d++) sc = fmaf(qs[w][d], ks[lane][d], sc);
        sc *= 0.125f;
        if (kk > qidx) sc = -1e30f;
        float tmax = warp_max(sc);
        float mnew = fmaxf(m, tmax);
        float p = expf(sc - mnew);
        float corr = expf(m - mnew);
        m = mnew;
        float psum = warp_sum(p);
        lsum = lsum*corr + psum;
        o0 *= corr; o1 *= corr;
#pragma unroll
        for (int j = 0; j < 32; j++) {
            float pj = __shfl_sync(0xffffffffu, p, j);
            o0 = fmaf(pj, vs[j][lane],    o0);
            o1 = fmaf(pj, vs[j][lane+32], o1);
        }
    }
    float inv = 1.f / lsum;
    y[((long)qidx*NH + h)*HD + lane]      = o0*inv;
    y[((long)qidx*NH + h)*HD + lane + 32] = o1*inv;
}

// ---------------- elementwise ----------------
// x += (t0 + t1) * gain   (sums split-K partials)
__global__ void axpy2_gain_kernel(float* __restrict__ x,
                                  const float* __restrict__ t0, const float* __restrict__ t1,
                                  const float* __restrict__ gain, int n)
{
    int i = blockIdx.x*256 + threadIdx.x;
    if (i < n) x[i] = fmaf(t0[i] + t1[i], gain[0], x[i]);
}
__global__ void silu_mul_kernel(float* __restrict__ a, const float* __restrict__ b, int n)
{
    int i = blockIdx.x*256 + threadIdx.x;
    if (i < n) {
        float g = a[i];
        a[i] = (g / (1.f + expf(-g))) * b[i];
    }
}
// x = x + (t0 + t1)*mg + ex*sk   (sums split-K partials)
__global__ void residual2p_kernel(float* __restrict__ x,
                                  const float* __restrict__ t0, const float* __restrict__ t1,
                                  const float* __restrict__ ex,
                                  const float* __restrict__ mg, const float* __restrict__ sk, int n)
{
    int i = blockIdx.x*256 + threadIdx.x;
    if (i < n) x[i] = x[i] + (t0[i] + t1[i])*mg[0] + ex[i]*sk[0];
}

// ---------------- launch ----------------
extern "C" void kernel_launch(void* const* d_in, const int* in_sizes, int n_in,
                              void* d_out, int out_size)
{
    const int*   ids        = (const int*)  d_in[0];
    const float* embed      = (const float*)d_in[1];
    const float* Wq         = (const float*)d_in[2];
    const float* Wk         = (const float*)d_in[3];
    const float* Wv         = (const float*)d_in[4];
    const float* Wo         = (const float*)d_in[5];
    const float* head_gain  = (const float*)d_in[6];
    const float* attn_gain  = (const float*)d_in[7];
    const float* Wg         = (const float*)d_in[8];
    const float* Wl         = (const float*)d_in[9];
    const float* Wr         = (const float*)d_in[10];
    const float* mlp_gain   = (const float*)d_in[11];
    const float* embed_skip = (const float*)d_in[12];
    const float* lm_head    = (const float*)d_in[13];
    const float* lm_gain    = (const float*)d_in[14];

    float *x,*ex,*ain,*q,*k,*v,*y,*tmp,*h1,*h2;
    cudaGetSymbolAddress((void**)&x,   g_x);
    cudaGetSymbolAddress((void**)&ex,  g_ex);
    cudaGetSymbolAddress((void**)&ain, g_ain);
    cudaGetSymbolAddress((void**)&q,   g_q);
    cudaGetSymbolAddress((void**)&k,   g_k);
    cudaGetSymbolAddress((void**)&v,   g_v);
    cudaGetSymbolAddress((void**)&y,   g_y);
    cudaGetSymbolAddress((void**)&tmp, g_tmp);
    cudaGetSymbolAddress((void**)&h1,  g_h1);
    cudaGetSymbolAddress((void**)&h2,  g_h2);
    float* tmp1 = tmp + SQ*DM;

    cudaFuncSetAttribute(gemm_mma<64>,  cudaFuncAttributeMaxDynamicSharedMemorySize, SMEM64);
    cudaFuncSetAttribute(gemm_mma<128>, cudaFuncAttributeMaxDynamicSharedMemorySize, SMEM128);

    dim3 g_qkv(DM/64,  SQ/128, 3);   // 16x8x3 = 384 CTAs, multi-B mode
    dim3 g_spl(DM/64,  SQ/128, 2);   // 16x8x2 = 256 CTAs, split-K mode
    dim3 g_ff (DFF/128, SQ/128, 2);  // 32x8x2 = 512 CTAs, multi-B mode
    dim3 g_lm (NV/128,  SQ/128, 1);  // 250x8  = 2000 CTAs
    dim3 g_rope(NH, SQ);
    dim3 g_attn(SQ/8, NH);
    int nd  = SQ*DM,  bd  = nd/256;
    int nff = SQ*DFF, bff = nff/256;

    embed_rms_kernel<<<SQ, 256>>>(ids, embed, x, ex);

    for (int l = 0; l < NL; l++) {
        rms_kernel<<<SQ, 256>>>(x, ain);
        // fused QKV: z selects weight + output buffer
        gemm_mma<64><<<g_qkv, 256, SMEM64>>>(ain,
            Wq + (long)l*DM*DM, Wk + (long)l*DM*DM, Wv + (long)l*DM*DM,
            q, k, v, DM, DM, nullptr, 0);
        rope_rms_kernel<<<g_rope, 32>>>(q, head_gain + l*NH);
        rope_rms_kernel<<<g_rope, 32>>>(k, nullptr);
        attn_kernel<<<g_attn, 256>>>(q, k, v, y);
        // Wo with split-K=2: partials in tmp, tmp1
        gemm_mma<64><<<g_spl, 256, SMEM64>>>(y,
            Wo + (long)l*DM*DM, nullptr, nullptr,
            tmp, tmp1, nullptr, DM, DM, nullptr, DM/2);
        axpy2_gain_kernel<<<bd, 256>>>(x, tmp, tmp1, attn_gain + l, nd);
        rms_kernel<<<SQ, 256>>>(x, ain);
        // fused gate+up: z selects Wg/Wl -> h1/h2
        gemm_mma<128><<<g_ff, 256, SMEM128>>>(ain,
            Wg + (long)l*DFF*DM, Wl + (long)l*DFF*DM, nullptr,
            h1, h2, nullptr, DM, DFF, nullptr, 0);
        silu_mul_kernel<<<bff, 256>>>(h1, h2, nff);
        // Wr with split-K=2 over K=4096
        gemm_mma<64><<<g_spl, 256, SMEM64>>>(h1,
            Wr + (long)l*DM*DFF, nullptr, nullptr,
            tmp, tmp1, nullptr, DFF, DM, nullptr, DFF/2);
        residual2p_kernel<<<bd, 256>>>(x, tmp, tmp1, ex, mlp_gain + l, embed_skip + l, nd);
    }

    rms_kernel<<<SQ, 256>>>(x, ain);
    gemm_mma<128><<<g_lm, 256, SMEM128>>>(ain, lm_head, nullptr, nullptr,
        (float*)d_out, nullptr, nullptr, DM, NV, lm_gain, 0);
}

// round 16
// speedup vs baseline: 3.6668x; 1.1479x over previous
#include <cuda_runtime.h>
#include <cuda_bf16.h>
#include <math.h>
#include <stdint.h>

#define SQ   1024
#define DM   1024
#define NH   16
#define HD   64
#define DFF  4096
#define NL   4
#define NV   32000

// ---------------- scratch (no allocations allowed) ----------------
__device__ float g_x  [SQ*DM];
__device__ float g_ex [SQ*DM];
__device__ float g_ain[SQ*DM];
__device__ float g_q  [SQ*DM];
__device__ float g_k  [SQ*DM];
__device__ float g_y  [SQ*DM];
__device__ float g_p  [6*SQ*DM];      // split-K / multi-op partials
__device__ float g_h  [2*SQ*DFF];     // gate | up

// ---------------- helpers ----------------
__device__ __forceinline__ uint32_t smem_u32(const void* p){
    uint32_t a;
    asm("{ .reg .u64 t; cvta.to.shared.u64 t, %1; cvt.u32.u64 %0, t; }" : "=r"(a) : "l"(p));
    return a;
}
__device__ __forceinline__ uint32_t f2tf32(float f){
    uint32_t u; asm("cvt.rna.tf32.f32 %0, %1;" : "=r"(u) : "f"(f)); return u;
}
__device__ __forceinline__ void cp16(uint32_t s, const void* g){
    asm volatile("cp.async.cg.shared.global [%0], [%1], 16;" :: "r"(s), "l"(g));
}
__device__ __forceinline__ void mma16n8k8(float* c, const uint32_t* a, const uint32_t* b){
    asm volatile("mma.sync.aligned.m16n8k8.row.col.f32.tf32.tf32.f32 "
        "{%0,%1,%2,%3}, {%4,%5,%6,%7}, {%8,%9}, {%0,%1,%2,%3};"
        : "+f"(c[0]), "+f"(c[1]), "+f"(c[2]), "+f"(c[3])
        : "r"(a[0]), "r"(a[1]), "r"(a[2]), "r"(a[3]), "r"(b[0]), "r"(b[1]));
}
__device__ __forceinline__ float warp_sum(float v){
#pragma unroll
    for (int o = 16; o; o >>= 1) v += __shfl_xor_sync(0xffffffffu, v, o);
    return v;
}
__device__ __forceinline__ float warp_max(float v){
#pragma unroll
    for (int o = 16; o; o >>= 1) v = fmaxf(v, __shfl_xor_sync(0xffffffffu, v, o));
    return v;
}

// ---------------- tf32 tensor-core GEMM: C = alpha * A[M,K] * B[N,K]^T ----------------
// grid = (N/128, M/128, ksplit*nops). z -> op = z/ksplit, kz = z%ksplit.
//   B = {B0,B1,B2}[op]; C = Cbase + op*cs_op + kz*cs_k; K range [kz*klen, (kz+1)*klen).
// 8 warps (2m x 4n), warp tile 64x32. BK=32. All row-major fp32.
#define BM 128
#define BN 128
#define BK 32
#define LDSF 36
#define GSMEM (4*BM*LDSF*4)   // As[2] + Bs[2] = 73728 bytes

__global__ __launch_bounds__(256, 2)
void gemm_mma(const float* __restrict__ A,
              const float* __restrict__ B0, const float* __restrict__ B1, const float* __restrict__ B2,
              float* __restrict__ Cbase, size_t cs_op, size_t cs_k,
              int K, int N, int klen, int ksplit,
              const float* __restrict__ alpha_ptr)
{
    extern __shared__ float sm[];
    float* As = sm;                    // [2][BM*LDSF]
    float* Bs = sm + 2*BM*LDSF;        // [2][BN*LDSF]

    int z  = blockIdx.z;
    int op = z / ksplit, kz = z - op*ksplit;
    const float* B = (op == 0) ? B0 : ((op == 1) ? B1 : B2);
    float* C = Cbase + (size_t)op*cs_op + (size_t)kz*cs_k;
    int k0 = kz * klen;

    int tid = threadIdx.x, lane = tid & 31, w = tid >> 5;
    int wm = (w & 1) * 64;             // 2 m-warps
    int wn = (w >> 1) * 32;            // 4 n-warps
    int lg = lane >> 2, lt = lane & 3;

    const float* Ab = A + (size_t)(blockIdx.y*BM)*K + k0;
    const float* Bb = B + (size_t)(blockIdx.x*BN)*K + k0;

    uint32_t bs0 = smem_u32(Bs);

    // B chunk 0 via cp.async (raw fp32)
#pragma unroll
    for (int j = 0; j < 4; j++){
        int slot = tid + 256*j, row = slot >> 3, c4 = slot & 7;
        cp16(bs0 + (row*LDSF + c4*4)*4, Bb + (size_t)row*K + c4*4);
    }
    asm volatile("cp.async.commit_group;");

    // A chunk 0 into registers
    float4 ra[4];
#pragma unroll
    for (int j = 0; j < 4; j++){
        int slot = tid + 256*j, row = slot >> 3, c4 = slot & 7;
        ra[j] = *(const float4*)(Ab + (size_t)row*K + c4*4);
    }

    float acc[4][4][4];
#pragma unroll
    for (int mt = 0; mt < 4; mt++)
#pragma unroll
        for (int nt = 0; nt < 4; nt++)
#pragma unroll
            for (int i = 0; i < 4; i++) acc[mt][nt][i] = 0.f;

    int nchunk = klen / BK;
    for (int c = 0; c < nchunk; c++){
        int st = c & 1;
        float* as = As + st*BM*LDSF;

        // store A (cvt.rna -> tf32) into smem
#pragma unroll
        for (int j = 0; j < 4; j++){
            int slot = tid + 256*j, row = slot >> 3, c4 = slot & 7;
            uint4 v = make_uint4(f2tf32(ra[j].x), f2tf32(ra[j].y), f2tf32(ra[j].z), f2tf32(ra[j].w));
            *(uint4*)(as + row*LDSF + c4*4) = v;
        }

        if (c + 1 < nchunk){
            const float* Bn = Bb + (size_t)(c+1)*BK;
            uint32_t bdst = bs0 + (uint32_t)(st^1)*BN*LDSF*4;
#pragma unroll
            for (int j = 0; j < 4; j++){
                int slot = tid + 256*j, row = slot >> 3, c4 = slot & 7;
                cp16(bdst + (row*LDSF + c4*4)*4, Bn + (size_t)row*K + c4*4);
            }
            asm volatile("cp.async.commit_group;");
            const float* An = Ab + (size_t)(c+1)*BK;
#pragma unroll
            for (int j = 0; j < 4; j++){
                int slot = tid + 256*j, row = slot >> 3, c4 = slot & 7;
                ra[j] = *(const float4*)(An + (size_t)row*K + c4*4);
            }
            asm volatile("cp.async.wait_group 1;");
        } else {
            asm volatile("cp.async.wait_group 0;");
        }
        __syncthreads();

        const uint32_t* asu = (const uint32_t*)(As + st*BM*LDSF);
        const float*    bsf = Bs + st*BN*LDSF;
#pragma unroll
        for (int ks = 0; ks < 4; ks++){
            int kb = ks * 8;
            uint32_t af[4][4];
#pragma unroll
            for (int mt = 0; mt < 4; mt++){
                const uint32_t* ap = asu + (wm + mt*16 + lg)*LDSF + kb + lt;
                af[mt][0] = ap[0];
                af[mt][1] = ap[8*LDSF];
                af[mt][2] = ap[4];
                af[mt][3] = ap[8*LDSF + 4];
            }
#pragma unroll
            for (int nt = 0; nt < 4; nt++){
                const float* bp = bsf + (wn + nt*8 + lg)*LDSF + kb + lt;
                uint32_t bf[2] = { f2tf32(bp[0]), f2tf32(bp[4]) };
#pragma unroll
                for (int mt = 0; mt < 4; mt++) mma16n8k8(acc[mt][nt], af[mt], bf);
            }
        }
        __syncthreads();   // protect Bs[st] from next iteration's cp.async
    }

    float alpha = alpha_ptr ? alpha_ptr[0] : 1.f;
    int row0 = blockIdx.y*BM + wm + lg;
    int col0 = blockIdx.x*BN + wn + 2*lt;
#pragma unroll
    for (int mt = 0; mt < 4; mt++){
#pragma unroll
        for (int nt = 0; nt < 4; nt++){
            float2 v0 = make_float2(alpha*acc[mt][nt][0], alpha*acc[mt][nt][1]);
            float2 v1 = make_float2(alpha*acc[mt][nt][2], alpha*acc[mt][nt][3]);
            *(float2*)(C + (size_t)(row0 + mt*16    )*N + col0 + nt*8) = v0;
            *(float2*)(C + (size_t)(row0 + mt*16 + 8)*N + col0 + nt*8) = v1;
        }
    }
}

// ---------------- embed gather + rms ----------------
__global__ void embed_rms_kernel(const int* __restrict__ ids,
                                 const float* __restrict__ embed,
                                 float* __restrict__ x, float* __restrict__ ex)
{
    __shared__ float red[8];
    int s = blockIdx.x;
    const float* row = embed + (size_t)ids[s] * DM;
    float ss = 0.f;
    for (int i = threadIdx.x; i < DM; i += 256) { float v = row[i]; ss += v*v; }
    ss = warp_sum(ss);
    if ((threadIdx.x & 31) == 0) red[threadIdx.x >> 5] = ss;
    __syncthreads();
    float tot = 0.f;
#pragma unroll
    for (int i = 0; i < 8; i++) tot += red[i];
    float rinv = rsqrtf(tot / (float)DM + 1e-5f);
    for (int i = threadIdx.x; i < DM; i += 256) {
        float v = row[i] * rinv;
        x[s*DM + i]  = v;
        ex[s*DM + i] = v;
    }
}

// ---------------- plain rms (layer-0 entry only) ----------------
__global__ void rms_kernel(const float* __restrict__ in, float* __restrict__ out)
{
    __shared__ float red[8];
    int s = blockIdx.x;
    const float* r = in + s*DM;
    float ss = 0.f;
    for (int i = threadIdx.x; i < DM; i += 256) { float v = r[i]; ss += v*v; }
    ss = warp_sum(ss);
    if ((threadIdx.x & 31) == 0) red[threadIdx.x >> 5] = ss;
    __syncthreads();
    float tot = 0.f;
#pragma unroll
    for (int i = 0; i < 8; i++) tot += red[i];
    float rinv = rsqrtf(tot / (float)DM + 1e-5f);
    for (int i = threadIdx.x; i < DM; i += 256) out[s*DM + i] = r[i]*rinv;
}

// ---------------- fused rope + head-rms for q AND k, summing split-K partials ----------------
// p layout: qp0|qp1|kp0|kp1|vp0|vp1, each SQ*DM. Warp per (s, h, q/k) task.
__global__ __launch_bounds__(256)
void rope_rms_fused(const float* __restrict__ p, float* __restrict__ q, float* __restrict__ k,
                    const float* __restrict__ gain)
{
    int wid  = threadIdx.x >> 5, lane = threadIdx.x & 31;
    int t  = blockIdx.x*8 + wid;           // 0..32767
    int s  = t >> 5;
    int r  = t & 31;
    int h  = r & 15;
    int qk = r >> 4;                        // 0 = q, 1 = k
    const size_t nd = (size_t)SQ*DM;
    const float* s0 = p + (size_t)qk*2*nd + ((size_t)s*NH + h)*HD;
    const float* s1 = s0 + nd;
    float x1 = s0[lane]      + s1[lane];
    float x2 = s0[lane + 32] + s1[lane + 32];
    float invf = expf(-((float)lane / 32.f) * 9.210340371976184f);
    float sn, c;
    sincosf((float)s * invf, &sn, &c);
    float o1 =  x1*c + x2*sn;
    float o2 = -x1*sn + x2*c;
    float ss = warp_sum(o1*o1 + o2*o2);
    float rinv = rsqrtf(ss / 64.f + 1e-5f);
    float g = qk ? 1.f : gain[h];
    float* dst = (qk ? k : q) + ((size_t)s*NH + h)*HD;
    dst[lane]      = o1*rinv*g;
    dst[lane + 32] = o2*rinv*g;
}

// ---------------- causal attention (flash-style, warp per query; V = vp0+vp1) ----------------
__global__ __launch_bounds__(256)
void attn_kernel(const float* __restrict__ q, const float* __restrict__ k,
                 const float* __restrict__ vp0, const float* __restrict__ vp1,
                 float* __restrict__ y)
{
    __shared__ float qs[8][65];
    __shared__ float ks[32][65];
    __shared__ float vs[32][65];
    int h   = blockIdx.y;
    int qb  = blockIdx.x;
    int w   = threadIdx.x >> 5;
    int lane= threadIdx.x & 31;
    int qidx = qb*8 + w;

    for (int i = threadIdx.x; i < 8*HD; i += 256) {
        int r = i >> 6, c = i & 63;
        qs[r][c] = q[(((size_t)(qb*8 + r))*NH + h)*HD + c];
    }

    float m = -1e30f, lsum = 0.f, o0 = 0.f, o1 = 0.f;
    int qmax = qb*8 + 7;
    for (int kt = 0; kt <= qmax; kt += 32) {
        __syncthreads();
        for (int i = threadIdx.x; i < 32*HD; i += 256) {
            int r = i >> 6, c = i & 63;
            size_t off = (((size_t)(kt + r))*NH + h)*HD + c;
            ks[r][c] = k[off];
            vs[r][c] = vp0[off] + vp1[off];
        }
        __syncthreads();
        int kk = kt + lane;
        float sc = 0.f;
#pragma unroll
        for (int d = 0; d < HD; d++) sc = fmaf(qs[w][d], ks[lane][d], sc);
        sc *= 0.125f;
        if (kk > qidx) sc = -1e30f;
        float tmax = warp_max(sc);
        float mnew = fmaxf(m, tmax);
        float pr = expf(sc - mnew);
        float corr = expf(m - mnew);
        m = mnew;
        float psum = warp_sum(pr);
        lsum = lsum*corr + psum;
        o0 *= corr; o1 *= corr;
#pragma unroll
        for (int j = 0; j < 32; j++) {
            float pj = __shfl_sync(0xffffffffu, pr, j);
            o0 = fmaf(pj, vs[j][lane],    o0);
            o1 = fmaf(pj, vs[j][lane+32], o1);
        }
    }
    float inv = 1.f / lsum;
    y[((size_t)qidx*NH + h)*HD + lane]      = o0*inv;
    y[((size_t)qidx*NH + h)*HD + lane + 32] = o1*inv;
}

// ---------------- fused: x += sum4(p)*gain;  ain = rms(x) ----------------
__global__ void axpy4_rms(float* __restrict__ x, const float* __restrict__ p,
                          float* __restrict__ ain, const float* __restrict__ gain)
{
    __shared__ float red[8];
    int s = blockIdx.x, tid = threadIdx.x;
    const size_t nd = (size_t)SQ*DM;
    size_t base = (size_t)s*DM + tid*4;
    float4 xv = *(float4*)(x + base);
    float4 p0 = *(const float4*)(p + base);
    float4 p1 = *(const float4*)(p + nd + base);
    float4 p2 = *(const float4*)(p + 2*nd + base);
    float4 p3 = *(const float4*)(p + 3*nd + base);
    float g = gain[0];
    xv.x += (p0.x + p1.x + p2.x + p3.x) * g;
    xv.y += (p0.y + p1.y + p2.y + p3.y) * g;
    xv.z += (p0.z + p1.z + p2.z + p3.z) * g;
    xv.w += (p0.w + p1.w + p2.w + p3.w) * g;
    *(float4*)(x + base) = xv;
    float ss = xv.x*xv.x + xv.y*xv.y + xv.z*xv.z + xv.w*xv.w;
    ss = warp_sum(ss);
    if ((tid & 31) == 0) red[tid >> 5] = ss;
    __syncthreads();
    float tot = 0.f;
#pragma unroll
    for (int i = 0; i < 8; i++) tot += red[i];
    float rinv = rsqrtf(tot / (float)DM + 1e-5f);
    float4 o = make_float4(xv.x*rinv, xv.y*rinv, xv.z*rinv, xv.w*rinv);
    *(float4*)(ain + base) = o;
}

// ---------------- fused: x += sum4(p)*mg + ex*sk;  ain = rms(x) ----------------
__global__ void residual4p_rms(float* __restrict__ x, const float* __restrict__ p,
                               const float* __restrict__ ex, float* __restrict__ ain,
                               const float* __restrict__ mg, const float* __restrict__ sk)
{
    __shared__ float red[8];
    int s = blockIdx.x, tid = threadIdx.x;
    const size_t nd = (size_t)SQ*DM;
    size_t base = (size_t)s*DM + tid*4;
    float4 xv = *(float4*)(x + base);
    float4 p0 = *(const float4*)(p + base);
    float4 p1 = *(const float4*)(p + nd + base);
    float4 p2 = *(const float4*)(p + 2*nd + base);
    float4 p3 = *(const float4*)(p + 3*nd + base);
    float4 ev = *(const float4*)(ex + base);
    float g = mg[0], e = sk[0];
    xv.x += (p0.x + p1.x + p2.x + p3.x)*g + ev.x*e;
    xv.y += (p0.y + p1.y + p2.y + p3.y)*g + ev.y*e;
    xv.z += (p0.z + p1.z + p2.z + p3.z)*g + ev.z*e;
    xv.w += (p0.w + p1.w + p2.w + p3.w)*g + ev.w*e;
    *(float4*)(x + base) = xv;
    float ss = xv.x*xv.x + xv.y*xv.y + xv.z*xv.z + xv.w*xv.w;
    ss = warp_sum(ss);
    if ((tid & 31) == 0) red[tid >> 5] = ss;
    __syncthreads();
    float tot = 0.f;
#pragma unroll
    for (int i = 0; i < 8; i++) tot += red[i];
    float rinv = rsqrtf(tot / (float)DM + 1e-5f);
    float4 o = make_float4(xv.x*rinv, xv.y*rinv, xv.z*rinv, xv.w*rinv);
    *(float4*)(ain + base) = o;
}

// ---------------- silu gate ----------------
__global__ void silu_mul_kernel(float* __restrict__ a, const float* __restrict__ b, int n)
{
    int i = blockIdx.x*256 + threadIdx.x;
    if (i < n) {
        float g = a[i];
        a[i] = (g / (1.f + expf(-g))) * b[i];
    }
}

// ---------------- launch ----------------
extern "C" void kernel_launch(void* const* d_in, const int* in_sizes, int n_in,
                              void* d_out, int out_size)
{
    const int*   ids        = (const int*)  d_in[0];
    const float* embed      = (const float*)d_in[1];
    const float* Wq         = (const float*)d_in[2];
    const float* Wk         = (const float*)d_in[3];
    const float* Wv         = (const float*)d_in[4];
    const float* Wo         = (const float*)d_in[5];
    const float* head_gain  = (const float*)d_in[6];
    const float* attn_gain  = (const float*)d_in[7];
    const float* Wg         = (const float*)d_in[8];
    const float* Wl         = (const float*)d_in[9];
    const float* Wr         = (const float*)d_in[10];
    const float* mlp_gain   = (const float*)d_in[11];
    const float* embed_skip = (const float*)d_in[12];
    const float* lm_head    = (const float*)d_in[13];
    const float* lm_gain    = (const float*)d_in[14];

    float *x,*ex,*ain,*q,*k,*y,*p,*h;
    cudaGetSymbolAddress((void**)&x,   g_x);
    cudaGetSymbolAddress((void**)&ex,  g_ex);
    cudaGetSymbolAddress((void**)&ain, g_ain);
    cudaGetSymbolAddress((void**)&q,   g_q);
    cudaGetSymbolAddress((void**)&k,   g_k);
    cudaGetSymbolAddress((void**)&y,   g_y);
    cudaGetSymbolAddress((void**)&p,   g_p);
    cudaGetSymbolAddress((void**)&h,   g_h);

    cudaFuncSetAttribute(gemm_mma, cudaFuncAttributeMaxDynamicSharedMemorySize, GSMEM);

    const size_t nd  = (size_t)SQ*DM;
    const size_t nh_ = (size_t)SQ*DFF;
    int nff = SQ*DFF, bff = nff/256;

    dim3 g_qkv(DM/BN,  SQ/BM, 6);   // 3 ops x split-K2 = 384 CTAs
    dim3 g_wo (DM/BN,  SQ/BM, 4);   // split-K4 = 256 CTAs
    dim3 g_ff (DFF/BN, SQ/BM, 2);   // 2 ops   = 512 CTAs
    dim3 g_wr (DM/BN,  SQ/BM, 4);   // split-K4 = 256 CTAs
    dim3 g_lm (NV/BN,  SQ/BM, 1);   // 2000 CTAs
    dim3 g_attn(SQ/8, NH);

    embed_rms_kernel<<<SQ, 256>>>(ids, embed, x, ex);
    rms_kernel<<<SQ, 256>>>(x, ain);          // layer-0 entry norm

    for (int l = 0; l < NL; l++) {
        // QKV: op in {Wq,Wk,Wv} x split-K2 -> p[op*2+kz]
        gemm_mma<<<g_qkv, 256, GSMEM>>>(ain,
            Wq + (size_t)l*DM*DM, Wk + (size_t)l*DM*DM, Wv + (size_t)l*DM*DM,
            p, 2*nd, nd, DM, DM, DM/2, 2, nullptr);
        rope_rms_fused<<<SQ*NH*2/8, 256>>>(p, q, k, head_gain + l*NH);
        attn_kernel<<<g_attn, 256>>>(q, k, p + 4*nd, p + 5*nd, y);
        // Wo split-K4 -> p[0..3]
        gemm_mma<<<g_wo, 256, GSMEM>>>(y,
            Wo + (size_t)l*DM*DM, nullptr, nullptr,
            p, 0, nd, DM, DM, DM/4, 4, nullptr);
        axpy4_rms<<<SQ, 256>>>(x, p, ain, attn_gain + l);
        // gate + up fused -> h[0], h[1]
        gemm_mma<<<g_ff, 256, GSMEM>>>(ain,
            Wg + (size_t)l*DFF*DM, Wl + (size_t)l*DFF*DM, nullptr,
            h, nh_, 0, DM, DFF, DM, 1, nullptr);
        silu_mul_kernel<<<bff, 256>>>(h, h + nh_, nff);
        // Wr split-K4 over K=4096 -> p[0..3]
        gemm_mma<<<g_wr, 256, GSMEM>>>(h,
            Wr + (size_t)l*DM*DFF, nullptr, nullptr,
            p, 0, nd, DFF, DM, DFF/4, 4, nullptr);
        residual4p_rms<<<SQ, 256>>>(x, p, ex, ain, mlp_gain + l, embed_skip + l);
    }

    // lm_head (ain already = rms(x) from last residual4p_rms)
    gemm_mma<<<g_lm, 256, GSMEM>>>(ain, lm_head, nullptr, nullptr,
        (float*)d_out, 0, 0, DM, NV, DM, 1, lm_gain);
}

// round 17
// speedup vs baseline: 3.7593x; 1.0252x over previous
#include <cuda_runtime.h>
#include <cuda_bf16.h>
#include <math.h>
#include <stdint.h>

#define SQ   1024
#define DM   1024
#define NH   16
#define HD   64
#define DFF  4096
#define NL   4
#define NV   32000

// ---------------- scratch (no allocations allowed) ----------------
__device__ float g_x  [SQ*DM];
__device__ float g_ex [SQ*DM];
__device__ float g_ain[SQ*DM];
__device__ float g_q  [SQ*DM];
__device__ float g_k  [SQ*DM];
__device__ float g_y  [SQ*DM];
__device__ float g_p  [6*SQ*DM];      // split-K / multi-op partials
__device__ float g_h  [2*SQ*DFF];     // gate | up

// ---------------- helpers ----------------
__device__ __forceinline__ uint32_t smem_u32(const void* p){
    uint32_t a;
    asm("{ .reg .u64 t; cvta.to.shared.u64 t, %1; cvt.u32.u64 %0, t; }" : "=r"(a) : "l"(p));
    return a;
}
__device__ __forceinline__ uint32_t f2tf32(float f){
    uint32_t u; asm("cvt.rna.tf32.f32 %0, %1;" : "=r"(u) : "f"(f)); return u;
}
__device__ __forceinline__ void cp16(uint32_t s, const void* g){
    asm volatile("cp.async.cg.shared.global [%0], [%1], 16;" :: "r"(s), "l"(g));
}
__device__ __forceinline__ void mma16n8k8(float* c, const uint32_t* a, const uint32_t* b){
    asm volatile("mma.sync.aligned.m16n8k8.row.col.f32.tf32.tf32.f32 "
        "{%0,%1,%2,%3}, {%4,%5,%6,%7}, {%8,%9}, {%0,%1,%2,%3};"
        : "+f"(c[0]), "+f"(c[1]), "+f"(c[2]), "+f"(c[3])
        : "r"(a[0]), "r"(a[1]), "r"(a[2]), "r"(a[3]), "r"(b[0]), "r"(b[1]));
}
__device__ __forceinline__ float warp_sum(float v){
#pragma unroll
    for (int o = 16; o; o >>= 1) v += __shfl_xor_sync(0xffffffffu, v, o);
    return v;
}
__device__ __forceinline__ float warp_max(float v){
#pragma unroll
    for (int o = 16; o; o >>= 1) v = fmaxf(v, __shfl_xor_sync(0xffffffffu, v, o));
    return v;
}

// ---------------- tf32 tensor-core GEMM: C = alpha * A[M,K] * B[N,K]^T ----------------
// grid = (N/128, M/128, ksplit*nops). z -> op = z/ksplit, kz = z%ksplit.
//   B = {B0,B1,B2}[op]; C = Cbase + op*cs_op + kz*cs_k; K range [kz*klen, (kz+1)*klen).
// 8 warps (2m x 4n), warp tile 64x32. BK=32.
// Pipeline: A 2-stage reg-prefetch + cvt store; B 3-stage cp.async (2 chunks ahead);
// ONE __syncthreads per chunk (covers both WAR hazards).
#define BM 128
#define BN 128
#define BK 32
#define LDSF 36
#define GSMEM ((2*BM + 3*BN)*LDSF*4)   // A[2] + B[3] = 92160 bytes

__global__ __launch_bounds__(256, 2)
void gemm_mma(const float* __restrict__ A,
              const float* __restrict__ B0, const float* __restrict__ B1, const float* __restrict__ B2,
              float* __restrict__ Cbase, size_t cs_op, size_t cs_k,
              int K, int N, int klen, int ksplit,
              const float* __restrict__ alpha_ptr)
{
    extern __shared__ float sm[];
    float* As = sm;                    // [2][BM*LDSF]
    float* Bs = sm + 2*BM*LDSF;        // [3][BN*LDSF]

    int z  = blockIdx.z;
    int op = z / ksplit, kz = z - op*ksplit;
    const float* B = (op == 0) ? B0 : ((op == 1) ? B1 : B2);
    float* C = Cbase + (size_t)op*cs_op + (size_t)kz*cs_k;
    int k0 = kz * klen;

    int tid = threadIdx.x, lane = tid & 31, w = tid >> 5;
    int wm = (w & 1) * 64;             // 2 m-warps
    int wn = (w >> 1) * 32;            // 4 n-warps
    int lg = lane >> 2, lt = lane & 3;

    const float* Ab = A + (size_t)(blockIdx.y*BM)*K + k0;
    const float* Bb = B + (size_t)(blockIdx.x*BN)*K + k0;

    uint32_t bs0 = smem_u32(Bs);
    int nchunk = klen / BK;

    // B chunks 0 and 1 via cp.async into stages 0,1
#pragma unroll
    for (int j = 0; j < 4; j++){
        int slot = tid + 256*j, row = slot >> 3, c4 = slot & 7;
        cp16(bs0 + (row*LDSF + c4*4)*4, Bb + (size_t)row*K + c4*4);
    }
    asm volatile("cp.async.commit_group;");
    {
        const float* B1p = Bb + BK;
        uint32_t bdst = bs0 + (uint32_t)(BN*LDSF*4);
#pragma unroll
        for (int j = 0; j < 4; j++){
            int slot = tid + 256*j, row = slot >> 3, c4 = slot & 7;
            cp16(bdst + (row*LDSF + c4*4)*4, B1p + (size_t)row*K + c4*4);
        }
    }
    asm volatile("cp.async.commit_group;");

    // A chunk 0 into registers
    float4 ra[4];
#pragma unroll
    for (int j = 0; j < 4; j++){
        int slot = tid + 256*j, row = slot >> 3, c4 = slot & 7;
        ra[j] = *(const float4*)(Ab + (size_t)row*K + c4*4);
    }

    float acc[4][4][4];
#pragma unroll
    for (int mt = 0; mt < 4; mt++)
#pragma unroll
        for (int nt = 0; nt < 4; nt++)
#pragma unroll
            for (int i = 0; i < 4; i++) acc[mt][nt][i] = 0.f;

    int astage = 0, bstage = 0;
    for (int c = 0; c < nchunk; c++){
        float* as = As + astage*BM*LDSF;

        // store A(c) (cvt.rna -> tf32); safe: chunk c-2 readers done (passed barrier c-1)
#pragma unroll
        for (int j = 0; j < 4; j++){
            int slot = tid + 256*j, row = slot >> 3, c4 = slot & 7;
            uint4 v = make_uint4(f2tf32(ra[j].x), f2tf32(ra[j].y), f2tf32(ra[j].z), f2tf32(ra[j].w));
            *(uint4*)(as + row*LDSF + c4*4) = v;
        }
        // prefetch A(c+1) into registers
        if (c + 1 < nchunk){
            const float* An = Ab + (size_t)(c+1)*BK;
#pragma unroll
            for (int j = 0; j < 4; j++){
                int slot = tid + 256*j, row = slot >> 3, c4 = slot & 7;
                ra[j] = *(const float4*)(An + (size_t)row*K + c4*4);
            }
        }

        // B(c) must be resident; B(c+1) may remain in flight
        asm volatile("cp.async.wait_group 1;");
        __syncthreads();               // the ONE barrier per chunk

        // issue B(c+2) into stage (bstage+2)%3 — that buffer's readers (chunk c-1) are done
        {
            int bs2 = bstage + 2; if (bs2 >= 3) bs2 -= 3;
            if (c + 2 < nchunk){
                const float* Bn = Bb + (size_t)(c+2)*BK;
                uint32_t bdst = bs0 + (uint32_t)bs2*BN*LDSF*4;
#pragma unroll
                for (int j = 0; j < 4; j++){
                    int slot = tid + 256*j, row = slot >> 3, c4 = slot & 7;
                    cp16(bdst + (row*LDSF + c4*4)*4, Bn + (size_t)row*K + c4*4);
                }
            }
            asm volatile("cp.async.commit_group;");   // always commit (group may be empty)
        }

        const uint32_t* asu = (const uint32_t*)as;
        const float*    bsf = Bs + bstage*BN*LDSF;
#pragma unroll
        for (int ks = 0; ks < 4; ks++){
            int kb = ks * 8;
            uint32_t af[4][4];
#pragma unroll
            for (int mt = 0; mt < 4; mt++){
                const uint32_t* ap = asu + (wm + mt*16 + lg)*LDSF + kb + lt;
                af[mt][0] = ap[0];
                af[mt][1] = ap[8*LDSF];
                af[mt][2] = ap[4];
                af[mt][3] = ap[8*LDSF + 4];
            }
#pragma unroll
            for (int nt = 0; nt < 4; nt++){
                const float* bp = bsf + (wn + nt*8 + lg)*LDSF + kb + lt;
                uint32_t bf[2] = { f2tf32(bp[0]), f2tf32(bp[4]) };
#pragma unroll
                for (int mt = 0; mt < 4; mt++) mma16n8k8(acc[mt][nt], af[mt], bf);
            }
        }
        astage ^= 1;
        bstage++; if (bstage == 3) bstage = 0;
    }

    float alpha = alpha_ptr ? alpha_ptr[0] : 1.f;
    int row0 = blockIdx.y*BM + wm + lg;
    int col0 = blockIdx.x*BN + wn + 2*lt;
#pragma unroll
    for (int mt = 0; mt < 4; mt++){
#pragma unroll
        for (int nt = 0; nt < 4; nt++){
            float2 v0 = make_float2(alpha*acc[mt][nt][0], alpha*acc[mt][nt][1]);
            float2 v1 = make_float2(alpha*acc[mt][nt][2], alpha*acc[mt][nt][3]);
            *(float2*)(C + (size_t)(row0 + mt*16    )*N + col0 + nt*8) = v0;
            *(float2*)(C + (size_t)(row0 + mt*16 + 8)*N + col0 + nt*8) = v1;
        }
    }
}

// ---------------- embed gather + rms ----------------
__global__ void embed_rms_kernel(const int* __restrict__ ids,
                                 const float* __restrict__ embed,
                                 float* __restrict__ x, float* __restrict__ ex)
{
    __shared__ float red[8];
    int s = blockIdx.x;
    const float* row = embed + (size_t)ids[s] * DM;
    float ss = 0.f;
    for (int i = threadIdx.x; i < DM; i += 256) { float v = row[i]; ss += v*v; }
    ss = warp_sum(ss);
    if ((threadIdx.x & 31) == 0) red[threadIdx.x >> 5] = ss;
    __syncthreads();
    float tot = 0.f;
#pragma unroll
    for (int i = 0; i < 8; i++) tot += red[i];
    float rinv = rsqrtf(tot / (float)DM + 1e-5f);
    for (int i = threadIdx.x; i < DM; i += 256) {
        float v = row[i] * rinv;
        x[s*DM + i]  = v;
        ex[s*DM + i] = v;
    }
}

// ---------------- plain rms (layer-0 entry only) ----------------
__global__ void rms_kernel(const float* __restrict__ in, float* __restrict__ out)
{
    __shared__ float red[8];
    int s = blockIdx.x;
    const float* r = in + s*DM;
    float ss = 0.f;
    for (int i = threadIdx.x; i < DM; i += 256) { float v = r[i]; ss += v*v; }
    ss = warp_sum(ss);
    if ((threadIdx.x & 31) == 0) red[threadIdx.x >> 5] = ss;
    __syncthreads();
    float tot = 0.f;
#pragma unroll
    for (int i = 0; i < 8; i++) tot += red[i];
    float rinv = rsqrtf(tot / (float)DM + 1e-5f);
    for (int i = threadIdx.x; i < DM; i += 256) out[s*DM + i] = r[i]*rinv;
}

// ---------------- fused rope + head-rms for q AND k, summing split-K partials ----------------
// p layout: qp0|qp1|kp0|kp1|vp0|vp1, each SQ*DM. Warp per (s, h, q/k) task.
__global__ __launch_bounds__(256)
void rope_rms_fused(const float* __restrict__ p, float* __restrict__ q, float* __restrict__ k,
                    const float* __restrict__ gain)
{
    int wid  = threadIdx.x >> 5, lane = threadIdx.x & 31;
    int t  = blockIdx.x*8 + wid;           // 0..32767
    int s  = t >> 5;
    int r  = t & 31;
    int h  = r & 15;
    int qk = r >> 4;                        // 0 = q, 1 = k
    const size_t nd = (size_t)SQ*DM;
    const float* s0 = p + (size_t)qk*2*nd + ((size_t)s*NH + h)*HD;
    const float* s1 = s0 + nd;
    float x1 = s0[lane]      + s1[lane];
    float x2 = s0[lane + 32] + s1[lane + 32];
    float invf = expf(-((float)lane / 32.f) * 9.210340371976184f);
    float sn, c;
    sincosf((float)s * invf, &sn, &c);
    float o1 =  x1*c + x2*sn;
    float o2 = -x1*sn + x2*c;
    float ss = warp_sum(o1*o1 + o2*o2);
    float rinv = rsqrtf(ss / 64.f + 1e-5f);
    float g = qk ? 1.f : gain[h];
    float* dst = (qk ? k : q) + ((size_t)s*NH + h)*HD;
    dst[lane]      = o1*rinv*g;
    dst[lane + 32] = o2*rinv*g;
}

// ---------------- causal attention (flash-style, warp per query; V = vp0+vp1) ----------------
__global__ __launch_bounds__(256)
void attn_kernel(const float* __restrict__ q, const float* __restrict__ k,
                 const float* __restrict__ vp0, const float* __restrict__ vp1,
                 float* __restrict__ y)
{
    __shared__ float qs[8][65];
    __shared__ float ks[32][65];
    __shared__ float vs[32][65];
    int h   = blockIdx.y;
    int qb  = blockIdx.x;
    int w   = threadIdx.x >> 5;
    int lane= threadIdx.x & 31;
    int qidx = qb*8 + w;

    for (int i = threadIdx.x; i < 8*HD; i += 256) {
        int r = i >> 6, c = i & 63;
        qs[r][c] = q[(((size_t)(qb*8 + r))*NH + h)*HD + c];
    }

    float m = -1e30f, lsum = 0.f, o0 = 0.f, o1 = 0.f;
    int qmax = qb*8 + 7;
    for (int kt = 0; kt <= qmax; kt += 32) {
        __syncthreads();
        for (int i = threadIdx.x; i < 32*HD; i += 256) {
            int r = i >> 6, c = i & 63;
            size_t off = (((size_t)(kt + r))*NH + h)*HD + c;
            ks[r][c] = k[off];
            vs[r][c] = vp0[off] + vp1[off];
        }
        __syncthreads();
        int kk = kt + lane;
        float sc = 0.f;
#pragma unroll
        for (int d = 0; d < HD; d++) sc = fmaf(qs[w][d], ks[lane][d], sc);
        sc *= 0.125f;
        if (kk > qidx) sc = -1e30f;
        float tmax = warp_max(sc);
        float mnew = fmaxf(m, tmax);
        float pr = expf(sc - mnew);
        float corr = expf(m - mnew);
        m = mnew;
        float psum = warp_sum(pr);
        lsum = lsum*corr + psum;
        o0 *= corr; o1 *= corr;
#pragma unroll
        for (int j = 0; j < 32; j++) {
            float pj = __shfl_sync(0xffffffffu, pr, j);
            o0 = fmaf(pj, vs[j][lane],    o0);
            o1 = fmaf(pj, vs[j][lane+32], o1);
        }
    }
    float inv = 1.f / lsum;
    y[((size_t)qidx*NH + h)*HD + lane]      = o0*inv;
    y[((size_t)qidx*NH + h)*HD + lane + 32] = o1*inv;
}

// ---------------- fused: x += sum4(p)*gain;  ain = rms(x) ----------------
__global__ void axpy4_rms(float* __restrict__ x, const float* __restrict__ p,
                          float* __restrict__ ain, const float* __restrict__ gain)
{
    __shared__ float red[8];
    int s = blockIdx.x, tid = threadIdx.x;
    const size_t nd = (size_t)SQ*DM;
    size_t base = (size_t)s*DM + tid*4;
    float4 xv = *(float4*)(x + base);
    float4 p0 = *(const float4*)(p + base);
    float4 p1 = *(const float4*)(p + nd + base);
    float4 p2 = *(const float4*)(p + 2*nd + base);
    float4 p3 = *(const float4*)(p + 3*nd + base);
    float g = gain[0];
    xv.x += (p0.x + p1.x + p2.x + p3.x) * g;
    xv.y += (p0.y + p1.y + p2.y + p3.y) * g;
    xv.z += (p0.z + p1.z + p2.z + p3.z) * g;
    xv.w += (p0.w + p1.w + p2.w + p3.w) * g;
    *(float4*)(x + base) = xv;
    float ss = xv.x*xv.x + xv.y*xv.y + xv.z*xv.z + xv.w*xv.w;
    ss = warp_sum(ss);
    if ((tid & 31) == 0) red[tid >> 5] = ss;
    __syncthreads();
    float tot = 0.f;
#pragma unroll
    for (int i = 0; i < 8; i++) tot += red[i];
    float rinv = rsqrtf(tot / (float)DM + 1e-5f);
    float4 o = make_float4(xv.x*rinv, xv.y*rinv, xv.z*rinv, xv.w*rinv);
    *(float4*)(ain + base) = o;
}

// ---------------- fused: x += sum4(p)*mg + ex*sk;  ain = rms(x) ----------------
__global__ void residual4p_rms(float* __restrict__ x, const float* __restrict__ p,
                               const float* __restrict__ ex, float* __restrict__ ain,
                               const float* __restrict__ mg, const float* __restrict__ sk)
{
    __shared__ float red[8];
    int s = blockIdx.x, tid = threadIdx.x;
    const size_t nd = (size_t)SQ*DM;
    size_t base = (size_t)s*DM + tid*4;
    float4 xv = *(float4*)(x + base);
    float4 p0 = *(const float4*)(p + base);
    float4 p1 = *(const float4*)(p + nd + base);
    float4 p2 = *(const float4*)(p + 2*nd + base);
    float4 p3 = *(const float4*)(p + 3*nd + base);
    float4 ev = *(const float4*)(ex + base);
    float g = mg[0], e = sk[0];
    xv.x += (p0.x + p1.x + p2.x + p3.x)*g + ev.x*e;
    xv.y += (p0.y + p1.y + p2.y + p3.y)*g + ev.y*e;
    xv.z += (p0.z + p1.z + p2.z + p3.z)*g + ev.z*e;
    xv.w += (p0.w + p1.w + p2.w + p3.w)*g + ev.w*e;
    *(float4*)(x + base) = xv;
    float ss = xv.x*xv.x + xv.y*xv.y + xv.z*xv.z + xv.w*xv.w;
    ss = warp_sum(ss);
    if ((tid & 31) == 0) red[tid >> 5] = ss;
    __syncthreads();
    float tot = 0.f;
#pragma unroll
    for (int i = 0; i < 8; i++) tot += red[i];
    float rinv = rsqrtf(tot / (float)DM + 1e-5f);
    float4 o = make_float4(xv.x*rinv, xv.y*rinv, xv.z*rinv, xv.w*rinv);
    *(float4*)(ain + base) = o;
}

// ---------------- silu gate ----------------
__global__ void silu_mul_kernel(float* __restrict__ a, const float* __restrict__ b, int n)
{
    int i = blockIdx.x*256 + threadIdx.x;
    if (i < n) {
        float g = a[i];
        a[i] = (g / (1.f + expf(-g))) * b[i];
    }
}

// ---------------- launch ----------------
extern "C" void kernel_launch(void* const* d_in, const int* in_sizes, int n_in,
                              void* d_out, int out_size)
{
    const int*   ids        = (const int*)  d_in[0];
    const float* embed      = (const float*)d_in[1];
    const float* Wq         = (const float*)d_in[2];
    const float* Wk         = (const float*)d_in[3];
    const float* Wv         = (const float*)d_in[4];
    const float* Wo         = (const float*)d_in[5];
    const float* head_gain  = (const float*)d_in[6];
    const float* attn_gain  = (const float*)d_in[7];
    const float* Wg         = (const float*)d_in[8];
    const float* Wl         = (const float*)d_in[9];
    const float* Wr         = (const float*)d_in[10];
    const float* mlp_gain   = (const float*)d_in[11];
    const float* embed_skip = (const float*)d_in[12];
    const float* lm_head    = (const float*)d_in[13];
    const float* lm_gain    = (const float*)d_in[14];

    float *x,*ex,*ain,*q,*k,*y,*p,*h;
    cudaGetSymbolAddress((void**)&x,   g_x);
    cudaGetSymbolAddress((void**)&ex,  g_ex);
    cudaGetSymbolAddress((void**)&ain, g_ain);
    cudaGetSymbolAddress((void**)&q,   g_q);
    cudaGetSymbolAddress((void**)&k,   g_k);
    cudaGetSymbolAddress((void**)&y,   g_y);
    cudaGetSymbolAddress((void**)&p,   g_p);
    cudaGetSymbolAddress((void**)&h,   g_h);

    cudaFuncSetAttribute(gemm_mma, cudaFuncAttributeMaxDynamicSharedMemorySize, GSMEM);

    const size_t nd  = (size_t)SQ*DM;
    const size_t nh_ = (size_t)SQ*DFF;
    int nff = SQ*DFF, bff = nff/256;

    dim3 g_qkv(DM/BN,  SQ/BM, 6);   // 3 ops x split-K2 = 384 CTAs
    dim3 g_wo (DM/BN,  SQ/BM, 4);   // split-K4 = 256 CTAs
    dim3 g_ff (DFF/BN, SQ/BM, 2);   // 2 ops   = 512 CTAs
    dim3 g_wr (DM/BN,  SQ/BM, 4);   // split-K4 = 256 CTAs
    dim3 g_lm (NV/BN,  SQ/BM, 1);   // 2000 CTAs
    dim3 g_attn(SQ/8, NH);

    embed_rms_kernel<<<SQ, 256>>>(ids, embed, x, ex);
    rms_kernel<<<SQ, 256>>>(x, ain);          // layer-0 entry norm

    for (int l = 0; l < NL; l++) {
        // QKV: op in {Wq,Wk,Wv} x split-K2 -> p[op*2+kz]
        gemm_mma<<<g_qkv, 256, GSMEM>>>(ain,
            Wq + (size_t)l*DM*DM, Wk + (size_t)l*DM*DM, Wv + (size_t)l*DM*DM,
            p, 2*nd, nd, DM, DM, DM/2, 2, nullptr);
        rope_rms_fused<<<SQ*NH*2/8, 256>>>(p, q, k, head_gain + l*NH);
        attn_kernel<<<g_attn, 256>>>(q, k, p + 4*nd, p + 5*nd, y);
        // Wo split-K4 -> p[0..3]
        gemm_mma<<<g_wo, 256, GSMEM>>>(y,
            Wo + (size_t)l*DM*DM, nullptr, nullptr,
            p, 0, nd, DM, DM, DM/4, 4, nullptr);
        axpy4_rms<<<SQ, 256>>>(x, p, ain, attn_gain + l);
        // gate + up fused -> h[0], h[1]
        gemm_mma<<<g_ff, 256, GSMEM>>>(ain,
            Wg + (size_t)l*DFF*DM, Wl + (size_t)l*DFF*DM, nullptr,
            h, nh_, 0, DM, DFF, DM, 1, nullptr);
        silu_mul_kernel<<<bff, 256>>>(h, h + nh_, nff);
        // Wr split-K4 over K=4096 -> p[0..3]
        gemm_mma<<<g_wr, 256, GSMEM>>>(h,
            Wr + (size_t)l*DM*DFF, nullptr, nullptr,
            p, 0, nd, DFF, DM, DFF/4, 4, nullptr);
        residual4p_rms<<<SQ, 256>>>(x, p, ex, ain, mlp_gain + l, embed_skip + l);
    }

    // lm_head (ain already = rms(x) from last residual4p_rms)
    gemm_mma<<<g_lm, 256, GSMEM>>>(ain, lm_head, nullptr, nullptr,
        (float*)d_out, 0, 0, DM, NV, DM, 1, lm_gain);
}